// round 15
// baseline (speedup 1.0000x reference)
#include <cuda_runtime.h>
#include <math.h>
#include <cstdint>

typedef unsigned long long ull;

// Problem constants
#define L_STEPS 128
#define NB 64
#define HID 4096            // 32*16*8
#define T1S 128             // t1 row stride (words)
#define L_PER 16            // timesteps per xw worker CTA

// XW scratch: (L, 3, N, 4096) fp32 = 402 MB.
__device__ float g_xw[(size_t)L_STEPS * 3 * NB * HID];
// Per-(n,l) ready flags. Producer sets 1 (release); consumer resets 0 after use.
__device__ int g_flag[NB * L_STEPS];

__device__ __forceinline__ void fma2(ull& acc, ull a, ull b) {
    asm("fma.rn.f32x2 %0, %1, %2, %0;" : "+l"(acc) : "l"(a), "l"(b));
}
__device__ __forceinline__ ull dup2(float x) {
    ull r; asm("mov.b64 %0, {%1, %1};" : "=l"(r) : "f"(x)); return r;
}
__device__ __forceinline__ ull pack2(float lo, float hi) {
    ull r; asm("mov.b64 %0, {%1, %2};" : "=l"(r) : "f"(lo), "f"(hi)); return r;
}
__device__ __forceinline__ void unpack2(float& lo, float& hi, ull v) {
    asm("mov.b64 {%0, %1}, %2;" : "=f"(lo), "=f"(hi) : "l"(v));
}
__device__ __forceinline__ uint32_t smem_u32(const void* p) {
    uint32_t a;
    asm("{ .reg .u64 t; cvta.to.shared.u64 t, %1; cvt.u32.u64 %0, t; }" : "=r"(a) : "l"(p));
    return a;
}
__device__ __forceinline__ uint32_t mapa_u32(uint32_t addr, uint32_t rank) {
    uint32_t r;
    asm("mapa.shared::cluster.u32 %0, %1, %2;" : "=r"(r) : "r"(addr), "r"(rank));
    return r;
}
__device__ __forceinline__ void st_cluster_b64(uint32_t addr, ull v) {
    asm volatile("st.shared::cluster.b64 [%0], %1;" :: "r"(addr), "l"(v) : "memory");
}
__device__ __forceinline__ int ld_acquire(const int* p) {
    int v;
    asm volatile("ld.acquire.gpu.global.b32 %0, [%1];" : "=r"(v) : "l"(p) : "memory");
    return v;
}

// ---------------------------------------------------------------------------
// Fused single launch: CTAs [0, 128) = GRU clusters (2 per sample);
// CTAs [128, 640) = XW workers (8 per sample, 16 timesteps each).
// XW workers set g_flag[n][l] when XW[l] is in g_xw; GRU consumers spin
// (idle warp 12) and reset after consumption -> graph-replay deterministic.
// 98 KB SMEM + <=64 regs -> 2 CTAs/SM: xw streams fill gru's idle issue slots.
// ---------------------------------------------------------------------------
__global__ __launch_bounds__(512, 2) __cluster_dims__(2, 1, 1)
void fused_kernel(
    const float* __restrict__ x,    // (N, L, 4096)
    const float* __restrict__ W1,   // (3,32,32)
    const float* __restrict__ W2,   // (3,16,16)
    const float* __restrict__ W3,   // (3,8,8)
    const float* __restrict__ U1,   // (3,32,32)
    const float* __restrict__ U2,   // (3,16,16)
    const float* __restrict__ U3,   // (3,8,8)
    float* __restrict__ out)        // outs (N,L,4096) then h_last (N,4096)
{
    extern __shared__ float sm[];
    const int t = threadIdx.x;
    const int warp = t >> 5, lane = t & 31;

    if (blockIdx.x < 2 * NB) {
        // =================== GRU role (R14 gru + flag sync) ===================
        float* h0  = sm;                 // 4096
        float* h1  = h0 + 4096;          // 4096
        float* t1  = h1 + 4096;          // 48*T1S = 6144   rows r = g*16+dd
        float* u1t = t1 + 6144;          // 1536
        float* w2t = u1t + 1536;         // 768
        float* u3s = w2t + 768;          // 192

        const int n    = blockIdx.x >> 1;
        const int rank = blockIdx.x & 1;
        const int peer = rank ^ 1;

        for (int i = t; i < 4096; i += 512) h0[i] = 0.f;
        for (int i = t; i < 1536; i += 512) {
            int g = i >> 9, rem = i & 511, dd = rem >> 5, a = rem & 31;
            u1t[a * 48 + g * 16 + dd] = U1[((g * 32) + rank * 16 + dd) * 32 + a];
        }
        for (int i = t; i < 768; i += 512) {
            int g = i >> 8, rem = i & 255, e = rem >> 4, b = rem & 15;
            w2t[g * 256 + b * 16 + e] = U2[i];
        }
        for (int i = t; i < 192; i += 512) u3s[i] = U3[i];
        __syncthreads();

        const uint32_t h0a = smem_u32(h0);
        const uint32_t h1a = smem_u32(h1);

        const int r0  = warp * 4;
        const int bc0 = lane * 4;
        const int e2 = lane >> 1;
        const int c4 = (lane & 1) * 4;
        const int f0 = c4;
        const bool loLane = ((lane & 1) == 0);
        const int gbase = ((rank * 16 + warp) * 16 + e2) * 8 + f0;

        float* hc = h0;
        float* hn = h1;

        for (int l = 0; l < L_STEPS; l++) {
            // ---- phase A: warps 0-11 do p1; warp 12 lane 0 handles flags ----
            if (warp < 12) {
                ull acc2[4][2];
#pragma unroll
                for (int j = 0; j < 4; j++) { acc2[j][0] = 0; acc2[j][1] = 0; }
#pragma unroll
                for (int a = 0; a < 32; a++) {
                    ulonglong2 hv = *reinterpret_cast<const ulonglong2*>(&hc[a * 128 + bc0]);
                    float4 wv = *reinterpret_cast<const float4*>(&u1t[a * 48 + r0]);
                    ull w0 = dup2(wv.x), w1 = dup2(wv.y), w2 = dup2(wv.z), w3 = dup2(wv.w);
                    fma2(acc2[0][0], w0, hv.x);  fma2(acc2[0][1], w0, hv.y);
                    fma2(acc2[1][0], w1, hv.x);  fma2(acc2[1][1], w1, hv.y);
                    fma2(acc2[2][0], w2, hv.x);  fma2(acc2[2][1], w2, hv.y);
                    fma2(acc2[3][0], w3, hv.x);  fma2(acc2[3][1], w3, hv.y);
                }
#pragma unroll
                for (int j = 0; j < 4; j++) {
                    ulonglong2 st; st.x = acc2[j][0]; st.y = acc2[j][1];
                    *reinterpret_cast<ulonglong2*>(&t1[(r0 + j) * T1S + bc0]) = st;
                }
            } else if (t == 384) {
                if (l > 0 && rank == 0)
                    *(volatile int*)&g_flag[n * L_STEPS + (l - 1)] = 0;   // consumed
                while (ld_acquire(&g_flag[n * L_STEPS + l]) == 0) {}      // wait producer
            }
            __syncthreads();   // t1 ready + XW[l] visibility (via spinner's acquire)

            // ---- phase B: issue XW loads early, consume at the end ----
            float4 xf0 = *reinterpret_cast<const float4*>(
                g_xw + (((size_t)l * 3 + 0) * NB + n) * HID + gbase);
            float4 xf1 = *reinterpret_cast<const float4*>(
                g_xw + (((size_t)l * 3 + 1) * NB + n) * HID + gbase);
            float4 xf2 = *reinterpret_cast<const float4*>(
                g_xw + (((size_t)l * 3 + 2) * NB + n) * HID + gbase);

            float hu[3][4];
#pragma unroll
            for (int g = 0; g < 3; g++) {
                const float* t1r = t1 + (g * 16 + warp) * T1S;
                const float* w2g = w2t + g * 256;
                ull a0 = 0, a1 = 0;
#pragma unroll
                for (int b = 0; b < 16; b++) {
                    ulonglong2 tv = *reinterpret_cast<const ulonglong2*>(&t1r[b * 8 + c4]);
                    ull wd = dup2(w2g[b * 16 + e2]);
                    fma2(a0, wd, tv.x);
                    fma2(a1, wd, tv.y);
                }
                float m0, m1, m2, m3;
                unpack2(m0, m1, a0);
                unpack2(m2, m3, a1);
                float o0 = __shfl_xor_sync(0xffffffffu, m0, 1);
                float o1 = __shfl_xor_sync(0xffffffffu, m1, 1);
                float o2 = __shfl_xor_sync(0xffffffffu, m2, 1);
                float o3 = __shfl_xor_sync(0xffffffffu, m3, 1);
                float col[8];
                col[0] = loLane ? m0 : o0;  col[1] = loLane ? m1 : o1;
                col[2] = loLane ? m2 : o2;  col[3] = loLane ? m3 : o3;
                col[4] = loLane ? o0 : m0;  col[5] = loLane ? o1 : m1;
                col[6] = loLane ? o2 : m2;  col[7] = loLane ? o3 : m3;

                const float* u3g = u3s + g * 64;
#pragma unroll
                for (int j = 0; j < 4; j++) {
                    float4 ua = *reinterpret_cast<const float4*>(&u3g[(f0 + j) * 8]);
                    float4 ub = *reinterpret_cast<const float4*>(&u3g[(f0 + j) * 8 + 4]);
                    hu[g][j] = ua.x * col[0] + ua.y * col[1] + ua.z * col[2] + ua.w * col[3]
                             + ub.x * col[4] + ub.y * col[5] + ub.z * col[6] + ub.w * col[7];
                }
            }

            float4 ho = *reinterpret_cast<const float4*>(&hc[gbase]);
            float hold[4] = {ho.x, ho.y, ho.z, ho.w};
            float xz[4] = {xf0.x, xf0.y, xf0.z, xf0.w};
            float xr[4] = {xf1.x, xf1.y, xf1.z, xf1.w};
            float xh[4] = {xf2.x, xf2.y, xf2.z, xf2.w};

            float res[4];
#pragma unroll
            for (int j = 0; j < 4; j++) {
                float z  = 1.f / (1.f + __expf(-(xz[j] + hu[0][j])));
                float r  = 1.f / (1.f + __expf(-(xr[j] + hu[1][j])));
                float ax = xh[j] + r * hu[2][j];
                float e2x = __expf(2.f * ax);
                float hh = 1.f - 2.f / (e2x + 1.f);      // tanh, NaN-safe
                res[j] = z * hold[j] + (1.f - z) * hh;
            }
            float4 r4 = make_float4(res[0], res[1], res[2], res[3]);
            *reinterpret_cast<float4*>(&hn[gbase]) = r4;

            {
                uint32_t hna = (l & 1) ? h0a : h1a;
                uint32_t ra = mapa_u32(hna + (uint32_t)gbase * 4u, (uint32_t)peer);
                st_cluster_b64(ra,     pack2(res[0], res[1]));
                st_cluster_b64(ra + 8, pack2(res[2], res[3]));
            }

            asm volatile("barrier.cluster.arrive.aligned;" ::: "memory");
            *reinterpret_cast<float4*>(out + ((size_t)n * L_STEPS + l) * HID + gbase) = r4;
            asm volatile("barrier.cluster.wait.aligned;"   ::: "memory");

            float* tmp = hc; hc = hn; hn = tmp;
        }

        if (t == 384 && rank == 0)
            *(volatile int*)&g_flag[n * L_STEPS + (L_STEPS - 1)] = 0;

        float* hl = out + (size_t)NB * L_STEPS * HID + (size_t)n * HID + rank * 2048;
        const float* hsrc = hc + rank * 2048;
        for (int i = t; i < 2048; i += 512) hl[i] = hsrc[i];

    } else {
        // =================== XW role (R14 xw + flag release) ===================
        float* xs  = sm;              // 2 x 4096
        float* t1  = xs + 8192;       // 96*T1S = 12288
        float* w1t = t1 + 12288;      // 3072
        float* w2t = w1t + 3072;      // 768
        float* w3s = w2t + 768;       // 192

        const int idx = blockIdx.x - 2 * NB;
        const int n   = idx >> 3;
        const int l0  = (idx & 7) * L_PER;

        for (int i = t; i < 3072; i += 512) {
            int g = i >> 10, rem = i & 1023, d = rem >> 5, a = rem & 31;
            w1t[a * 96 + g * 32 + d] = W1[i];
        }
        for (int i = t; i < 768; i += 512) {
            int g = i >> 8, rem = i & 255, e = rem >> 4, b = rem & 15;
            w2t[g * 256 + b * 16 + e] = W2[i];
        }
        for (int i = t; i < 192; i += 512) w3s[i] = W3[i];
        {
            const float4* xg4 = reinterpret_cast<const float4*>(
                x + ((size_t)n * L_STEPS + l0) * HID);
            float4* xs4 = reinterpret_cast<float4*>(xs);
            xs4[t] = xg4[t];
            xs4[t + 512] = xg4[t + 512];
        }
        __syncthreads();

        const int r0  = warp * 8;
        const int bc0 = lane * 4;
        const int e2  = lane >> 1;
        const int c4  = (lane & 1) * 4;
        const int f0  = c4;
        const bool loLane = ((lane & 1) == 0);

        for (int ll = 0; ll < L_PER; ll++) {
            const int l = l0 + ll;
            float* cur = xs + (ll & 1) * 4096;
            float* nxt = xs + ((ll & 1) ^ 1) * 4096;

            if (warp < 12) {
                ull acc[8][2];
#pragma unroll
                for (int j = 0; j < 8; j++) { acc[j][0] = 0; acc[j][1] = 0; }
#pragma unroll
                for (int a = 0; a < 32; a++) {
                    ulonglong2 xv = *reinterpret_cast<const ulonglong2*>(&cur[a * 128 + bc0]);
                    float4 wa = *reinterpret_cast<const float4*>(&w1t[a * 96 + r0]);
                    float4 wb = *reinterpret_cast<const float4*>(&w1t[a * 96 + r0 + 4]);
                    ull w0 = dup2(wa.x), w1 = dup2(wa.y), w2 = dup2(wa.z), w3 = dup2(wa.w);
                    ull w4 = dup2(wb.x), w5 = dup2(wb.y), w6 = dup2(wb.z), w7 = dup2(wb.w);
                    fma2(acc[0][0], w0, xv.x);  fma2(acc[0][1], w0, xv.y);
                    fma2(acc[1][0], w1, xv.x);  fma2(acc[1][1], w1, xv.y);
                    fma2(acc[2][0], w2, xv.x);  fma2(acc[2][1], w2, xv.y);
                    fma2(acc[3][0], w3, xv.x);  fma2(acc[3][1], w3, xv.y);
                    fma2(acc[4][0], w4, xv.x);  fma2(acc[4][1], w4, xv.y);
                    fma2(acc[5][0], w5, xv.x);  fma2(acc[5][1], w5, xv.y);
                    fma2(acc[6][0], w6, xv.x);  fma2(acc[6][1], w6, xv.y);
                    fma2(acc[7][0], w7, xv.x);  fma2(acc[7][1], w7, xv.y);
                }
#pragma unroll
                for (int j = 0; j < 8; j++) {
                    ulonglong2 st; st.x = acc[j][0]; st.y = acc[j][1];
                    *reinterpret_cast<ulonglong2*>(&t1[(r0 + j) * T1S + bc0]) = st;
                }
                __syncwarp();

#pragma unroll
                for (int j = 0; j < 8; j++) {
                    const int r = r0 + j;
                    const int g = r >> 5, d = r & 31;
                    const float* t1r = t1 + r * T1S;
                    const float* w2g = w2t + g * 256;
                    ull a0 = 0, a1 = 0;
#pragma unroll
                    for (int b = 0; b < 16; b++) {
                        ulonglong2 tv = *reinterpret_cast<const ulonglong2*>(&t1r[b * 8 + c4]);
                        ull wd = dup2(w2g[b * 16 + e2]);
                        fma2(a0, wd, tv.x);
                        fma2(a1, wd, tv.y);
                    }
                    float m0, m1, m2, m3;
                    unpack2(m0, m1, a0);
                    unpack2(m2, m3, a1);
                    float o0 = __shfl_xor_sync(0xffffffffu, m0, 1);
                    float o1 = __shfl_xor_sync(0xffffffffu, m1, 1);
                    float o2 = __shfl_xor_sync(0xffffffffu, m2, 1);
                    float o3 = __shfl_xor_sync(0xffffffffu, m3, 1);
                    float col[8];
                    col[0] = loLane ? m0 : o0;  col[1] = loLane ? m1 : o1;
                    col[2] = loLane ? m2 : o2;  col[3] = loLane ? m3 : o3;
                    col[4] = loLane ? o0 : m0;  col[5] = loLane ? o1 : m1;
                    col[6] = loLane ? o2 : m2;  col[7] = loLane ? o3 : m3;

                    const float* w3g = w3s + g * 64;
                    float o[4];
#pragma unroll
                    for (int jj = 0; jj < 4; jj++) {
                        float4 ua = *reinterpret_cast<const float4*>(&w3g[(f0 + jj) * 8]);
                        float4 ub = *reinterpret_cast<const float4*>(&w3g[(f0 + jj) * 8 + 4]);
                        o[jj] = ua.x * col[0] + ua.y * col[1] + ua.z * col[2] + ua.w * col[3]
                              + ub.x * col[4] + ub.y * col[5] + ub.z * col[6] + ub.w * col[7];
                    }
                    float* outg = g_xw + (((size_t)l * 3 + g) * NB + n) * HID
                                + (d * 16 + e2) * 8 + f0;
                    *reinterpret_cast<float4*>(outg) = make_float4(o[0], o[1], o[2], o[3]);
                }
            } else {
                if (ll + 1 < L_PER) {
                    const int tt = t - 384;     // 0..127
                    const float4* src = reinterpret_cast<const float4*>(
                        x + ((size_t)n * L_STEPS + l + 1) * HID);
                    float4* dst = reinterpret_cast<float4*>(nxt);
#pragma unroll
                    for (int q = 0; q < 8; q++)
                        dst[q * 128 + tt] = src[q * 128 + tt];
                }
            }
            __syncthreads();   // all XW[l] STGs + nxt buffer done

            if (t == 0) {
                __threadfence();                                   // release
                *(volatile int*)&g_flag[n * L_STEPS + l] = 1;
            }
        }
    }
}

// ---------------------------------------------------------------------------
extern "C" void kernel_launch(void* const* d_in, const int* in_sizes, int n_in,
                              void* d_out, int out_size)
{
    const float* x  = (const float*)d_in[0];
    const float* W1 = (const float*)d_in[1];
    const float* W2 = (const float*)d_in[2];
    const float* W3 = (const float*)d_in[3];
    const float* U1 = (const float*)d_in[4];
    const float* U2 = (const float*)d_in[5];
    const float* U3 = (const float*)d_in[6];
    float* out = (float*)d_out;

    // max(xw 24512, gru 16832) floats = 98048 bytes -> 2 CTAs/SM
    const int SMEM = (8192 + 12288 + 3072 + 768 + 192) * (int)sizeof(float);
    cudaFuncSetAttribute(fused_kernel,
                         cudaFuncAttributeMaxDynamicSharedMemorySize, SMEM);

    fused_kernel<<<2 * NB + 8 * NB, 512, SMEM>>>(x, W1, W2, W3, U1, U2, U3, out);
}

// round 16
// speedup vs baseline: 1.0503x; 1.0503x over previous
#include <cuda_runtime.h>
#include <math.h>
#include <cstdint>

typedef unsigned long long ull;

// Problem constants
#define L_STEPS 128
#define NB 64
#define HID 4096            // 32*16*8
#define T1S 128             // t1 row stride (words)
#define L_PER 16            // timesteps per xw CTA

// XW scratch: (L, 3, N, 4096) fp32 = 402 MB.
__device__ float g_xw[(size_t)L_STEPS * 3 * NB * HID];

__device__ __forceinline__ void fma2(ull& acc, ull a, ull b) {
    asm("fma.rn.f32x2 %0, %1, %2, %0;" : "+l"(acc) : "l"(a), "l"(b));
}
__device__ __forceinline__ ull dup2(float x) {
    ull r; asm("mov.b64 %0, {%1, %1};" : "=l"(r) : "f"(x)); return r;
}
__device__ __forceinline__ ull pack2(float lo, float hi) {
    ull r; asm("mov.b64 %0, {%1, %2};" : "=l"(r) : "f"(lo), "f"(hi)); return r;
}
__device__ __forceinline__ void unpack2(float& lo, float& hi, ull v) {
    asm("mov.b64 {%0, %1}, %2;" : "=f"(lo), "=f"(hi) : "l"(v));
}
__device__ __forceinline__ uint32_t smem_u32(const void* p) {
    uint32_t a;
    asm("{ .reg .u64 t; cvta.to.shared.u64 t, %1; cvt.u32.u64 %0, t; }" : "=r"(a) : "l"(p));
    return a;
}
__device__ __forceinline__ uint32_t mapa_u32(uint32_t addr, uint32_t rank) {
    uint32_t r;
    asm("mapa.shared::cluster.u32 %0, %1, %2;" : "=r"(r) : "r"(addr), "r"(rank));
    return r;
}
__device__ __forceinline__ void st_cluster_b64(uint32_t addr, ull v) {
    asm volatile("st.shared::cluster.b64 [%0], %1;" :: "r"(addr), "l"(v) : "memory");
}

// ---------------------------------------------------------------------------
// Stage 1: XW for 16 timesteps per CTA. Grid (NB, L/16), 512 threads.
// (R14-exact: warp-local p1->p2+p3 shuffle, no t2 SMEM; 98 KB -> 2 CTAs/SM)
// ---------------------------------------------------------------------------
__global__ __launch_bounds__(512) void xw_kernel(
    const float* __restrict__ x,
    const float* __restrict__ W1,   // (3,32,32)
    const float* __restrict__ W2,   // (3,16,16)
    const float* __restrict__ W3)   // (3,8,8)
{
    extern __shared__ float sm[];
    float* xs  = sm;              // 2 x 4096 (double buffer): x[a][b*8+c]
    float* t1  = xs + 8192;       // 96*T1S = 12288, rows r = g*32+d
    float* w1t = t1 + 12288;      // 3072: w1t[a*96 + g*32 + d] = W1[g,d,a]
    float* w2t = w1t + 3072;      // 768:  w2t[g*256 + b*16 + e] = W2[g,e,b]
    float* w3s = w2t + 768;       // 192

    const int t  = threadIdx.x;
    const int n  = blockIdx.x;
    const int l0 = blockIdx.y * L_PER;

    for (int i = t; i < 3072; i += 512) {
        int g = i >> 10, rem = i & 1023, d = rem >> 5, a = rem & 31;
        w1t[a * 96 + g * 32 + d] = W1[i];
    }
    for (int i = t; i < 768; i += 512) {
        int g = i >> 8, rem = i & 255, e = rem >> 4, b = rem & 15;
        w2t[g * 256 + b * 16 + e] = W2[i];
    }
    for (int i = t; i < 192; i += 512) w3s[i] = W3[i];
    {
        const float4* xg4 = reinterpret_cast<const float4*>(x + ((size_t)n * L_STEPS + l0) * HID);
        float4* xs4 = reinterpret_cast<float4*>(xs);
        xs4[t] = xg4[t];
        xs4[t + 512] = xg4[t + 512];
    }
    __syncthreads();

    const int warp = t >> 5, lane = t & 31;
    const int r0  = warp * 8;
    const int bc0 = lane * 4;
    const int e2  = lane >> 1;
    const int c4  = (lane & 1) * 4;
    const int f0  = c4;
    const bool loLane = ((lane & 1) == 0);

    for (int ll = 0; ll < L_PER; ll++) {
        const int l = l0 + ll;
        float* cur = xs + (ll & 1) * 4096;
        float* nxt = xs + ((ll & 1) ^ 1) * 4096;

        if (warp < 12) {
            ull acc[8][2];
#pragma unroll
            for (int j = 0; j < 8; j++) { acc[j][0] = 0; acc[j][1] = 0; }
#pragma unroll
            for (int a = 0; a < 32; a++) {
                ulonglong2 xv = *reinterpret_cast<const ulonglong2*>(&cur[a * 128 + bc0]);
                float4 wa = *reinterpret_cast<const float4*>(&w1t[a * 96 + r0]);
                float4 wb = *reinterpret_cast<const float4*>(&w1t[a * 96 + r0 + 4]);
                ull w0 = dup2(wa.x), w1 = dup2(wa.y), w2 = dup2(wa.z), w3 = dup2(wa.w);
                ull w4 = dup2(wb.x), w5 = dup2(wb.y), w6 = dup2(wb.z), w7 = dup2(wb.w);
                fma2(acc[0][0], w0, xv.x);  fma2(acc[0][1], w0, xv.y);
                fma2(acc[1][0], w1, xv.x);  fma2(acc[1][1], w1, xv.y);
                fma2(acc[2][0], w2, xv.x);  fma2(acc[2][1], w2, xv.y);
                fma2(acc[3][0], w3, xv.x);  fma2(acc[3][1], w3, xv.y);
                fma2(acc[4][0], w4, xv.x);  fma2(acc[4][1], w4, xv.y);
                fma2(acc[5][0], w5, xv.x);  fma2(acc[5][1], w5, xv.y);
                fma2(acc[6][0], w6, xv.x);  fma2(acc[6][1], w6, xv.y);
                fma2(acc[7][0], w7, xv.x);  fma2(acc[7][1], w7, xv.y);
            }
#pragma unroll
            for (int j = 0; j < 8; j++) {
                ulonglong2 st; st.x = acc[j][0]; st.y = acc[j][1];
                *reinterpret_cast<ulonglong2*>(&t1[(r0 + j) * T1S + bc0]) = st;
            }
            __syncwarp();

#pragma unroll
            for (int j = 0; j < 8; j++) {
                const int r = r0 + j;
                const int g = r >> 5, d = r & 31;
                const float* t1r = t1 + r * T1S;
                const float* w2g = w2t + g * 256;
                ull a0 = 0, a1 = 0;
#pragma unroll
                for (int b = 0; b < 16; b++) {
                    ulonglong2 tv = *reinterpret_cast<const ulonglong2*>(&t1r[b * 8 + c4]);
                    ull wd = dup2(w2g[b * 16 + e2]);
                    fma2(a0, wd, tv.x);
                    fma2(a1, wd, tv.y);
                }
                float m0, m1, m2, m3;
                unpack2(m0, m1, a0);
                unpack2(m2, m3, a1);
                float o0 = __shfl_xor_sync(0xffffffffu, m0, 1);
                float o1 = __shfl_xor_sync(0xffffffffu, m1, 1);
                float o2 = __shfl_xor_sync(0xffffffffu, m2, 1);
                float o3 = __shfl_xor_sync(0xffffffffu, m3, 1);
                float col[8];
                col[0] = loLane ? m0 : o0;  col[1] = loLane ? m1 : o1;
                col[2] = loLane ? m2 : o2;  col[3] = loLane ? m3 : o3;
                col[4] = loLane ? o0 : m0;  col[5] = loLane ? o1 : m1;
                col[6] = loLane ? o2 : m2;  col[7] = loLane ? o3 : m3;

                const float* w3g = w3s + g * 64;
                float o[4];
#pragma unroll
                for (int jj = 0; jj < 4; jj++) {
                    float4 ua = *reinterpret_cast<const float4*>(&w3g[(f0 + jj) * 8]);
                    float4 ub = *reinterpret_cast<const float4*>(&w3g[(f0 + jj) * 8 + 4]);
                    o[jj] = ua.x * col[0] + ua.y * col[1] + ua.z * col[2] + ua.w * col[3]
                          + ub.x * col[4] + ub.y * col[5] + ub.z * col[6] + ub.w * col[7];
                }
                float* outg = g_xw + (((size_t)l * 3 + g) * NB + n) * HID
                            + (d * 16 + e2) * 8 + f0;
                *reinterpret_cast<float4*>(outg) = make_float4(o[0], o[1], o[2], o[3]);
            }
        } else {
            if (ll + 1 < L_PER) {
                const int tt = t - 384;     // 0..127
                const float4* src = reinterpret_cast<const float4*>(
                    x + ((size_t)n * L_STEPS + l + 1) * HID);
                float4* dst = reinterpret_cast<float4*>(nxt);
#pragma unroll
                for (int q = 0; q < 8; q++)
                    dst[q * 128 + tt] = src[q * 128 + tt];
            }
        }
        __syncthreads();
    }
}

// ---------------------------------------------------------------------------
// Stage 2: GRU recurrence. CLUSTER OF 4 CTAs per sample (256 CTAs, 256 thr):
// small CTAs so >=2 independent clusters co-reside per SM (dual-stream latency
// hiding). CTA owns dd in [rank*8, rank*8+8). Phase A: warps 0-5 p1 (4 rows),
// warps 6-7 stage this step's XW slice GMEM->SMEM. Phase B: warps 0-7 = dd,
// R14-shape shuffle p2+p3 + gate combine. DSMEM publish to 3 peers; one
// cluster barrier per step.
// ---------------------------------------------------------------------------
__global__ __launch_bounds__(256, 3) __cluster_dims__(4, 1, 1)
void gru_kernel(
    const float* __restrict__ U1,   // (3,32,32)
    const float* __restrict__ U2,   // (3,16,16)
    const float* __restrict__ U3,   // (3,8,8)
    float* __restrict__ out)        // outs (N,L,4096) then h_last (N,4096)
{
    extern __shared__ float sm[];
    float* h0  = sm;                 // 4096
    float* h1  = h0 + 4096;          // 4096
    float* t1  = h1 + 4096;          // 24*T1S = 3072   rows r = g*8+dd
    float* xwS = t1 + 3072;          // 3072: xwS[g*1024 + (dd*16+e)*8+f]
    float* u1t = xwS + 3072;         // 768: u1t[a*24 + g*8 + dd] = U1[g, rank*8+dd, a]
    float* w2t = u1t + 768;          // 768: w2t[g*256 + b*16 + e] = U2[g,e,b]
    float* u3s = w2t + 768;          // 192

    const int t    = threadIdx.x;
    const int n    = blockIdx.x >> 2;
    const int rank = blockIdx.x & 3;

    for (int i = t; i < 4096; i += 256) h0[i] = 0.f;
    for (int i = t; i < 768; i += 256) {
        int a = i / 24, rem = i % 24, g = rem >> 3, dd = rem & 7;
        u1t[i] = U1[((g * 32) + rank * 8 + dd) * 32 + a];
    }
    for (int i = t; i < 768; i += 256) {
        int g = i >> 8, rem = i & 255, e = rem >> 4, b = rem & 15;
        w2t[g * 256 + b * 16 + e] = U2[i];
    }
    for (int i = t; i < 192; i += 256) u3s[i] = U3[i];
    __syncthreads();

    const uint32_t h0a = smem_u32(h0);
    const uint32_t h1a = smem_u32(h1);

    const int warp = t >> 5, lane = t & 31;
    // p1 (warps 0..5): 4 t1-rows each; lane -> 4 cols
    const int r0  = warp * 4;
    const int bc0 = lane * 4;
    // p2+p3 (warps 0..7, warp = dd): lane -> (e2, c/f-half)
    const int e2 = lane >> 1;
    const int c4 = (lane & 1) * 4;
    const int f0 = c4;
    const bool loLane = ((lane & 1) == 0);
    const int gbase = ((rank * 8 + warp) * 16 + e2) * 8 + f0;  // 4 global hidden elems
    const int lbase = (warp * 16 + e2) * 8 + f0;               // local slice index

    // hoisted DSMEM addresses for the 3 peers x 2 buffers
    uint32_t raP[3][2];
#pragma unroll
    for (int p = 0; p < 3; p++) {
        uint32_t pr = (uint32_t)((rank + 1 + p) & 3);
        raP[p][0] = mapa_u32(h1a + (uint32_t)gbase * 4u, pr);  // hn when l even
        raP[p][1] = mapa_u32(h0a + (uint32_t)gbase * 4u, pr);  // hn when l odd
    }

    float* hc = h0;
    float* hn = h1;

    for (int l = 0; l < L_STEPS; l++) {
        // ---- phase A ----
        if (warp < 6) {
            // p1: t1[r][bc] = sum_a u1t[a][r]*hc[a*128+bc], 4 rows
            ull acc2[4][2];
#pragma unroll
            for (int j = 0; j < 4; j++) { acc2[j][0] = 0; acc2[j][1] = 0; }
#pragma unroll
            for (int a = 0; a < 32; a++) {
                ulonglong2 hv = *reinterpret_cast<const ulonglong2*>(&hc[a * 128 + bc0]);
                float4 wv = *reinterpret_cast<const float4*>(&u1t[a * 24 + r0]);
                ull w0 = dup2(wv.x), w1 = dup2(wv.y), w2 = dup2(wv.z), w3 = dup2(wv.w);
                fma2(acc2[0][0], w0, hv.x);  fma2(acc2[0][1], w0, hv.y);
                fma2(acc2[1][0], w1, hv.x);  fma2(acc2[1][1], w1, hv.y);
                fma2(acc2[2][0], w2, hv.x);  fma2(acc2[2][1], w2, hv.y);
                fma2(acc2[3][0], w3, hv.x);  fma2(acc2[3][1], w3, hv.y);
            }
#pragma unroll
            for (int j = 0; j < 4; j++) {
                ulonglong2 st; st.x = acc2[j][0]; st.y = acc2[j][1];
                *reinterpret_cast<ulonglong2*>(&t1[(r0 + j) * T1S + bc0]) = st;
            }
        } else {
            // warps 6-7: stage this step's XW slice (3 x 1024 floats) into SMEM
            const int tt = t - 192;     // 0..63
#pragma unroll
            for (int g = 0; g < 3; g++) {
                const float4* src = reinterpret_cast<const float4*>(
                    g_xw + (((size_t)l * 3 + g) * NB + n) * HID + rank * 1024);
                float4* dst = reinterpret_cast<float4*>(xwS + g * 1024);
#pragma unroll
                for (int q = 0; q < 4; q++)
                    dst[q * 64 + tt] = src[q * 64 + tt];
            }
        }
        __syncthreads();

        // ---- phase B (all 8 warps, warp = dd): register t2 via shuffle ----
        float hu[3][4];
#pragma unroll
        for (int g = 0; g < 3; g++) {
            const float* t1r = t1 + (g * 8 + warp) * T1S;
            const float* w2g = w2t + g * 256;
            ull a0 = 0, a1 = 0;
#pragma unroll
            for (int b = 0; b < 16; b++) {
                ulonglong2 tv = *reinterpret_cast<const ulonglong2*>(&t1r[b * 8 + c4]);
                ull wd = dup2(w2g[b * 16 + e2]);
                fma2(a0, wd, tv.x);
                fma2(a1, wd, tv.y);
            }
            float m0, m1, m2, m3;
            unpack2(m0, m1, a0);
            unpack2(m2, m3, a1);
            float o0 = __shfl_xor_sync(0xffffffffu, m0, 1);
            float o1 = __shfl_xor_sync(0xffffffffu, m1, 1);
            float o2 = __shfl_xor_sync(0xffffffffu, m2, 1);
            float o3 = __shfl_xor_sync(0xffffffffu, m3, 1);
            float col[8];
            col[0] = loLane ? m0 : o0;  col[1] = loLane ? m1 : o1;
            col[2] = loLane ? m2 : o2;  col[3] = loLane ? m3 : o3;
            col[4] = loLane ? o0 : m0;  col[5] = loLane ? o1 : m1;
            col[6] = loLane ? o2 : m2;  col[7] = loLane ? o3 : m3;

            const float* u3g = u3s + g * 64;
#pragma unroll
            for (int j = 0; j < 4; j++) {
                float4 ua = *reinterpret_cast<const float4*>(&u3g[(f0 + j) * 8]);
                float4 ub = *reinterpret_cast<const float4*>(&u3g[(f0 + j) * 8 + 4]);
                hu[g][j] = ua.x * col[0] + ua.y * col[1] + ua.z * col[2] + ua.w * col[3]
                         + ub.x * col[4] + ub.y * col[5] + ub.z * col[6] + ub.w * col[7];
            }
        }

        // gate combine (XW from SMEM stage)
        float4 xf0 = *reinterpret_cast<const float4*>(&xwS[lbase]);
        float4 xf1 = *reinterpret_cast<const float4*>(&xwS[1024 + lbase]);
        float4 xf2 = *reinterpret_cast<const float4*>(&xwS[2048 + lbase]);
        float4 ho  = *reinterpret_cast<const float4*>(&hc[gbase]);
        float hold[4] = {ho.x, ho.y, ho.z, ho.w};
        float xz[4] = {xf0.x, xf0.y, xf0.z, xf0.w};
        float xr[4] = {xf1.x, xf1.y, xf1.z, xf1.w};
        float xh[4] = {xf2.x, xf2.y, xf2.z, xf2.w};

        float res[4];
#pragma unroll
        for (int j = 0; j < 4; j++) {
            float z  = 1.f / (1.f + __expf(-(xz[j] + hu[0][j])));
            float r  = 1.f / (1.f + __expf(-(xr[j] + hu[1][j])));
            float ax = xh[j] + r * hu[2][j];
            float e2x = __expf(2.f * ax);
            float hh = 1.f - 2.f / (e2x + 1.f);      // tanh, NaN-safe
            res[j] = z * hold[j] + (1.f - z) * hh;
        }
        float4 r4 = make_float4(res[0], res[1], res[2], res[3]);
        *reinterpret_cast<float4*>(&hn[gbase]) = r4;

        // publish our slice to the 3 peers' hn via DSMEM
        {
            ull lo = pack2(res[0], res[1]);
            ull hi = pack2(res[2], res[3]);
            const int par = l & 1;
#pragma unroll
            for (int p = 0; p < 3; p++) {
                st_cluster_b64(raP[p][par],     lo);
                st_cluster_b64(raP[p][par] + 8, hi);
            }
        }

        // split cluster barrier; out STG hidden between arrive and wait
        asm volatile("barrier.cluster.arrive.aligned;" ::: "memory");
        *reinterpret_cast<float4*>(out + ((size_t)n * L_STEPS + l) * HID + gbase) = r4;
        asm volatile("barrier.cluster.wait.aligned;"   ::: "memory");

        float* tmp = hc; hc = hn; hn = tmp;
    }

    // h_last: each CTA writes its own quarter
    float* hl = out + (size_t)NB * L_STEPS * HID + (size_t)n * HID + rank * 1024;
    const float* hsrc = hc + rank * 1024;
    for (int i = t; i < 1024; i += 256) hl[i] = hsrc[i];
}

// ---------------------------------------------------------------------------
extern "C" void kernel_launch(void* const* d_in, const int* in_sizes, int n_in,
                              void* d_out, int out_size)
{
    const float* x  = (const float*)d_in[0];
    const float* W1 = (const float*)d_in[1];
    const float* W2 = (const float*)d_in[2];
    const float* W3 = (const float*)d_in[3];
    const float* U1 = (const float*)d_in[4];
    const float* U2 = (const float*)d_in[5];
    const float* U3 = (const float*)d_in[6];
    float* out = (float*)d_out;

    const int SMEM1 = (8192 + 12288 + 3072 + 768 + 192) * (int)sizeof(float);   // 98 KB
    const int SMEM2 = (4096 * 2 + 3072 + 3072 + 768 + 768 + 192) * (int)sizeof(float); // 63 KB

    cudaFuncSetAttribute(xw_kernel,  cudaFuncAttributeMaxDynamicSharedMemorySize, SMEM1);
    cudaFuncSetAttribute(gru_kernel, cudaFuncAttributeMaxDynamicSharedMemorySize, SMEM2);

    dim3 grid1(NB, L_STEPS / L_PER);
    xw_kernel<<<grid1, 512, SMEM1>>>(x, W1, W2, W3);
    gru_kernel<<<NB * 4, 256, SMEM2>>>(U1, U2, U3, out);
}

// round 17
// speedup vs baseline: 1.2773x; 1.2161x over previous
#include <cuda_runtime.h>
#include <math.h>
#include <cstdint>

typedef unsigned long long ull;

// Problem constants
#define L_STEPS 128
#define NB 64
#define HID 4096            // 32*16*8
#define T1S 128             // t1 row stride (words)

// XW scratch: (L, 3, N, 4096) fp32 = 402 MB.
__device__ float g_xw[(size_t)L_STEPS * 3 * NB * HID];
// Per-(n,l) ready flags. Producer sets 1 (release); consumer resets 0 after use.
__device__ int g_flag[NB * L_STEPS];

__device__ __forceinline__ void fma2(ull& acc, ull a, ull b) {
    asm("fma.rn.f32x2 %0, %1, %2, %0;" : "+l"(acc) : "l"(a), "l"(b));
}
__device__ __forceinline__ ull dup2(float x) {
    ull r; asm("mov.b64 %0, {%1, %1};" : "=l"(r) : "f"(x)); return r;
}
__device__ __forceinline__ ull pack2(float lo, float hi) {
    ull r; asm("mov.b64 %0, {%1, %2};" : "=l"(r) : "f"(lo), "f"(hi)); return r;
}
__device__ __forceinline__ void unpack2(float& lo, float& hi, ull v) {
    asm("mov.b64 {%0, %1}, %2;" : "=f"(lo), "=f"(hi) : "l"(v));
}
__device__ __forceinline__ uint32_t smem_u32(const void* p) {
    uint32_t a;
    asm("{ .reg .u64 t; cvta.to.shared.u64 t, %1; cvt.u32.u64 %0, t; }" : "=r"(a) : "l"(p));
    return a;
}
__device__ __forceinline__ uint32_t mapa_u32(uint32_t addr, uint32_t rank) {
    uint32_t r;
    asm("mapa.shared::cluster.u32 %0, %1, %2;" : "=r"(r) : "r"(addr), "r"(rank));
    return r;
}
__device__ __forceinline__ void st_cluster_b64(uint32_t addr, ull v) {
    asm volatile("st.shared::cluster.b64 [%0], %1;" :: "r"(addr), "l"(v) : "memory");
}
__device__ __forceinline__ int ld_acquire(const int* p) {
    int v;
    asm volatile("ld.acquire.gpu.global.b32 %0, [%1];" : "=r"(v) : "l"(p) : "memory");
    return v;
}

// ---------------------------------------------------------------------------
// Fused single launch, ALL CTAs resident in wave 1 (256 <= 296 slots):
//   CTAs [0, 128)   = GRU clusters (2 per sample, R14-exact + flag waits)
//   CTAs [128, 256) = XW producers: 2 per sample, parity-interleaved l
//                     (producer (n,par) computes l = par, par+2, ..., 126+par)
// Producer pair delivers ~2 timesteps per xw-step -> consumer never starves.
// 98 KB SMEM + 64 regs -> 2 CTAs/SM: ~1 gru + 1 xw per SM, independent
// streams fill each other's stall cycles.
// ---------------------------------------------------------------------------
__global__ __launch_bounds__(512, 2) __cluster_dims__(2, 1, 1)
void fused_kernel(
    const float* __restrict__ x,    // (N, L, 4096)
    const float* __restrict__ W1,   // (3,32,32)
    const float* __restrict__ W2,   // (3,16,16)
    const float* __restrict__ W3,   // (3,8,8)
    const float* __restrict__ U1,   // (3,32,32)
    const float* __restrict__ U2,   // (3,16,16)
    const float* __restrict__ U3,   // (3,8,8)
    float* __restrict__ out)        // outs (N,L,4096) then h_last (N,4096)
{
    extern __shared__ float sm[];
    const int t = threadIdx.x;
    const int warp = t >> 5, lane = t & 31;

    if (blockIdx.x < 2 * NB) {
        // =================== GRU role (R14 gru + flag sync) ===================
        float* h0  = sm;                 // 4096
        float* h1  = h0 + 4096;          // 4096
        float* t1  = h1 + 4096;          // 48*T1S = 6144   rows r = g*16+dd
        float* u1t = t1 + 6144;          // 1536
        float* w2t = u1t + 1536;         // 768
        float* u3s = w2t + 768;          // 192

        const int n    = blockIdx.x >> 1;
        const int rank = blockIdx.x & 1;
        const int peer = rank ^ 1;

        for (int i = t; i < 4096; i += 512) h0[i] = 0.f;
        for (int i = t; i < 1536; i += 512) {
            int g = i >> 9, rem = i & 511, dd = rem >> 5, a = rem & 31;
            u1t[a * 48 + g * 16 + dd] = U1[((g * 32) + rank * 16 + dd) * 32 + a];
        }
        for (int i = t; i < 768; i += 512) {
            int g = i >> 8, rem = i & 255, e = rem >> 4, b = rem & 15;
            w2t[g * 256 + b * 16 + e] = U2[i];
        }
        for (int i = t; i < 192; i += 512) u3s[i] = U3[i];
        __syncthreads();

        const uint32_t h0a = smem_u32(h0);
        const uint32_t h1a = smem_u32(h1);

        const int r0  = warp * 4;
        const int bc0 = lane * 4;
        const int e2 = lane >> 1;
        const int c4 = (lane & 1) * 4;
        const int f0 = c4;
        const bool loLane = ((lane & 1) == 0);
        const int gbase = ((rank * 16 + warp) * 16 + e2) * 8 + f0;

        float* hc = h0;
        float* hn = h1;

        for (int l = 0; l < L_STEPS; l++) {
            // ---- phase A: warps 0-11 p1; thread 384 handles flags ----
            if (warp < 12) {
                ull acc2[4][2];
#pragma unroll
                for (int j = 0; j < 4; j++) { acc2[j][0] = 0; acc2[j][1] = 0; }
#pragma unroll
                for (int a = 0; a < 32; a++) {
                    ulonglong2 hv = *reinterpret_cast<const ulonglong2*>(&hc[a * 128 + bc0]);
                    float4 wv = *reinterpret_cast<const float4*>(&u1t[a * 48 + r0]);
                    ull w0 = dup2(wv.x), w1 = dup2(wv.y), w2 = dup2(wv.z), w3 = dup2(wv.w);
                    fma2(acc2[0][0], w0, hv.x);  fma2(acc2[0][1], w0, hv.y);
                    fma2(acc2[1][0], w1, hv.x);  fma2(acc2[1][1], w1, hv.y);
                    fma2(acc2[2][0], w2, hv.x);  fma2(acc2[2][1], w2, hv.y);
                    fma2(acc2[3][0], w3, hv.x);  fma2(acc2[3][1], w3, hv.y);
                }
#pragma unroll
                for (int j = 0; j < 4; j++) {
                    ulonglong2 st; st.x = acc2[j][0]; st.y = acc2[j][1];
                    *reinterpret_cast<ulonglong2*>(&t1[(r0 + j) * T1S + bc0]) = st;
                }
            } else if (t == 384) {
                if (l > 0 && rank == 0)
                    *(volatile int*)&g_flag[n * L_STEPS + (l - 1)] = 0;   // consumed
                while (ld_acquire(&g_flag[n * L_STEPS + l]) == 0) {}      // wait producer
            }
            __syncthreads();   // t1 ready + XW[l] visibility (spinner's acquire)

            // ---- phase B: issue XW loads early, consume at the end ----
            float4 xf0 = *reinterpret_cast<const float4*>(
                g_xw + (((size_t)l * 3 + 0) * NB + n) * HID + gbase);
            float4 xf1 = *reinterpret_cast<const float4*>(
                g_xw + (((size_t)l * 3 + 1) * NB + n) * HID + gbase);
            float4 xf2 = *reinterpret_cast<const float4*>(
                g_xw + (((size_t)l * 3 + 2) * NB + n) * HID + gbase);

            float hu[3][4];
#pragma unroll
            for (int g = 0; g < 3; g++) {
                const float* t1r = t1 + (g * 16 + warp) * T1S;
                const float* w2g = w2t + g * 256;
                ull a0 = 0, a1 = 0;
#pragma unroll
                for (int b = 0; b < 16; b++) {
                    ulonglong2 tv = *reinterpret_cast<const ulonglong2*>(&t1r[b * 8 + c4]);
                    ull wd = dup2(w2g[b * 16 + e2]);
                    fma2(a0, wd, tv.x);
                    fma2(a1, wd, tv.y);
                }
                float m0, m1, m2, m3;
                unpack2(m0, m1, a0);
                unpack2(m2, m3, a1);
                float o0 = __shfl_xor_sync(0xffffffffu, m0, 1);
                float o1 = __shfl_xor_sync(0xffffffffu, m1, 1);
                float o2 = __shfl_xor_sync(0xffffffffu, m2, 1);
                float o3 = __shfl_xor_sync(0xffffffffu, m3, 1);
                float col[8];
                col[0] = loLane ? m0 : o0;  col[1] = loLane ? m1 : o1;
                col[2] = loLane ? m2 : o2;  col[3] = loLane ? m3 : o3;
                col[4] = loLane ? o0 : m0;  col[5] = loLane ? o1 : m1;
                col[6] = loLane ? o2 : m2;  col[7] = loLane ? o3 : m3;

                const float* u3g = u3s + g * 64;
#pragma unroll
                for (int j = 0; j < 4; j++) {
                    float4 ua = *reinterpret_cast<const float4*>(&u3g[(f0 + j) * 8]);
                    float4 ub = *reinterpret_cast<const float4*>(&u3g[(f0 + j) * 8 + 4]);
                    hu[g][j] = ua.x * col[0] + ua.y * col[1] + ua.z * col[2] + ua.w * col[3]
                             + ub.x * col[4] + ub.y * col[5] + ub.z * col[6] + ub.w * col[7];
                }
            }

            float4 ho = *reinterpret_cast<const float4*>(&hc[gbase]);
            float hold[4] = {ho.x, ho.y, ho.z, ho.w};
            float xz[4] = {xf0.x, xf0.y, xf0.z, xf0.w};
            float xr[4] = {xf1.x, xf1.y, xf1.z, xf1.w};
            float xh[4] = {xf2.x, xf2.y, xf2.z, xf2.w};

            float res[4];
#pragma unroll
            for (int j = 0; j < 4; j++) {
                float z  = 1.f / (1.f + __expf(-(xz[j] + hu[0][j])));
                float r  = 1.f / (1.f + __expf(-(xr[j] + hu[1][j])));
                float ax = xh[j] + r * hu[2][j];
                float e2x = __expf(2.f * ax);
                float hh = 1.f - 2.f / (e2x + 1.f);      // tanh, NaN-safe
                res[j] = z * hold[j] + (1.f - z) * hh;
            }
            float4 r4 = make_float4(res[0], res[1], res[2], res[3]);
            *reinterpret_cast<float4*>(&hn[gbase]) = r4;

            {
                uint32_t hna = (l & 1) ? h0a : h1a;
                uint32_t ra = mapa_u32(hna + (uint32_t)gbase * 4u, (uint32_t)peer);
                st_cluster_b64(ra,     pack2(res[0], res[1]));
                st_cluster_b64(ra + 8, pack2(res[2], res[3]));
            }

            asm volatile("barrier.cluster.arrive.aligned;" ::: "memory");
            *reinterpret_cast<float4*>(out + ((size_t)n * L_STEPS + l) * HID + gbase) = r4;
            asm volatile("barrier.cluster.wait.aligned;"   ::: "memory");

            float* tmp = hc; hc = hn; hn = tmp;
        }

        if (t == 384 && rank == 0)
            *(volatile int*)&g_flag[n * L_STEPS + (L_STEPS - 1)] = 0;

        float* hl = out + (size_t)NB * L_STEPS * HID + (size_t)n * HID + rank * 2048;
        const float* hsrc = hc + rank * 2048;
        for (int i = t; i < 2048; i += 512) hl[i] = hsrc[i];

    } else {
        // ============== XW producer role: (n, parity), 64 timesteps ==============
        float* xs  = sm;              // 2 x 4096 (ring over iterations)
        float* t1  = xs + 8192;       // 96*T1S = 12288
        float* w1t = t1 + 12288;      // 3072
        float* w2t = w1t + 3072;      // 768
        float* w3s = w2t + 768;       // 192

        const int idx = blockIdx.x - 2 * NB;
        const int n   = idx >> 1;
        const int par = idx & 1;      // produces l = par, par+2, ...

        for (int i = t; i < 3072; i += 512) {
            int g = i >> 10, rem = i & 1023, d = rem >> 5, a = rem & 31;
            w1t[a * 96 + g * 32 + d] = W1[i];
        }
        for (int i = t; i < 768; i += 512) {
            int g = i >> 8, rem = i & 255, e = rem >> 4, b = rem & 15;
            w2t[g * 256 + b * 16 + e] = W2[i];
        }
        for (int i = t; i < 192; i += 512) w3s[i] = W3[i];
        {
            const float4* xg4 = reinterpret_cast<const float4*>(
                x + ((size_t)n * L_STEPS + par) * HID);
            float4* xs4 = reinterpret_cast<float4*>(xs);
            xs4[t] = xg4[t];
            xs4[t + 512] = xg4[t + 512];
        }
        __syncthreads();

        const int r0  = warp * 8;
        const int bc0 = lane * 4;
        const int e2  = lane >> 1;
        const int c4  = (lane & 1) * 4;
        const int f0  = c4;
        const bool loLane = ((lane & 1) == 0);

        for (int it = 0; it < 64; it++) {
            const int l = par + it * 2;
            float* cur = xs + (it & 1) * 4096;
            float* nxt = xs + ((it & 1) ^ 1) * 4096;

            if (warp < 12) {
                ull acc[8][2];
#pragma unroll
                for (int j = 0; j < 8; j++) { acc[j][0] = 0; acc[j][1] = 0; }
#pragma unroll
                for (int a = 0; a < 32; a++) {
                    ulonglong2 xv = *reinterpret_cast<const ulonglong2*>(&cur[a * 128 + bc0]);
                    float4 wa = *reinterpret_cast<const float4*>(&w1t[a * 96 + r0]);
                    float4 wb = *reinterpret_cast<const float4*>(&w1t[a * 96 + r0 + 4]);
                    ull w0 = dup2(wa.x), w1 = dup2(wa.y), w2 = dup2(wa.z), w3 = dup2(wa.w);
                    ull w4 = dup2(wb.x), w5 = dup2(wb.y), w6 = dup2(wb.z), w7 = dup2(wb.w);
                    fma2(acc[0][0], w0, xv.x);  fma2(acc[0][1], w0, xv.y);
                    fma2(acc[1][0], w1, xv.x);  fma2(acc[1][1], w1, xv.y);
                    fma2(acc[2][0], w2, xv.x);  fma2(acc[2][1], w2, xv.y);
                    fma2(acc[3][0], w3, xv.x);  fma2(acc[3][1], w3, xv.y);
                    fma2(acc[4][0], w4, xv.x);  fma2(acc[4][1], w4, xv.y);
                    fma2(acc[5][0], w5, xv.x);  fma2(acc[5][1], w5, xv.y);
                    fma2(acc[6][0], w6, xv.x);  fma2(acc[6][1], w6, xv.y);
                    fma2(acc[7][0], w7, xv.x);  fma2(acc[7][1], w7, xv.y);
                }
#pragma unroll
                for (int j = 0; j < 8; j++) {
                    ulonglong2 st; st.x = acc[j][0]; st.y = acc[j][1];
                    *reinterpret_cast<ulonglong2*>(&t1[(r0 + j) * T1S + bc0]) = st;
                }
                __syncwarp();

#pragma unroll
                for (int j = 0; j < 8; j++) {
                    const int r = r0 + j;
                    const int g = r >> 5, d = r & 31;
                    const float* t1r = t1 + r * T1S;
                    const float* w2g = w2t + g * 256;
                    ull a0 = 0, a1 = 0;
#pragma unroll
                    for (int b = 0; b < 16; b++) {
                        ulonglong2 tv = *reinterpret_cast<const ulonglong2*>(&t1r[b * 8 + c4]);
                        ull wd = dup2(w2g[b * 16 + e2]);
                        fma2(a0, wd, tv.x);
                        fma2(a1, wd, tv.y);
                    }
                    float m0, m1, m2, m3;
                    unpack2(m0, m1, a0);
                    unpack2(m2, m3, a1);
                    float o0 = __shfl_xor_sync(0xffffffffu, m0, 1);
                    float o1 = __shfl_xor_sync(0xffffffffu, m1, 1);
                    float o2 = __shfl_xor_sync(0xffffffffu, m2, 1);
                    float o3 = __shfl_xor_sync(0xffffffffu, m3, 1);
                    float col[8];
                    col[0] = loLane ? m0 : o0;  col[1] = loLane ? m1 : o1;
                    col[2] = loLane ? m2 : o2;  col[3] = loLane ? m3 : o3;
                    col[4] = loLane ? o0 : m0;  col[5] = loLane ? o1 : m1;
                    col[6] = loLane ? o2 : m2;  col[7] = loLane ? o3 : m3;

                    const float* w3g = w3s + g * 64;
                    float o[4];
#pragma unroll
                    for (int jj = 0; jj < 4; jj++) {
                        float4 ua = *reinterpret_cast<const float4*>(&w3g[(f0 + jj) * 8]);
                        float4 ub = *reinterpret_cast<const float4*>(&w3g[(f0 + jj) * 8 + 4]);
                        o[jj] = ua.x * col[0] + ua.y * col[1] + ua.z * col[2] + ua.w * col[3]
                              + ub.x * col[4] + ub.y * col[5] + ub.z * col[6] + ub.w * col[7];
                    }
                    float* outg = g_xw + (((size_t)l * 3 + g) * NB + n) * HID
                                + (d * 16 + e2) * 8 + f0;
                    *reinterpret_cast<float4*>(outg) = make_float4(o[0], o[1], o[2], o[3]);
                }
            } else {
                // warps 12-15: copy x[l+2] GMEM -> nxt buffer
                if (it + 1 < 64) {
                    const int tt = t - 384;     // 0..127
                    const float4* src = reinterpret_cast<const float4*>(
                        x + ((size_t)n * L_STEPS + (l + 2)) * HID);
                    float4* dst = reinterpret_cast<float4*>(nxt);
#pragma unroll
                    for (int q = 0; q < 8; q++)
                        dst[q * 128 + tt] = src[q * 128 + tt];
                }
            }
            __syncthreads();   // all XW[l] STGs + nxt buffer done

            if (t == 0) {
                __threadfence();                                   // release
                *(volatile int*)&g_flag[n * L_STEPS + l] = 1;
            }
        }
    }
}

// ---------------------------------------------------------------------------
extern "C" void kernel_launch(void* const* d_in, const int* in_sizes, int n_in,
                              void* d_out, int out_size)
{
    const float* x  = (const float*)d_in[0];
    const float* W1 = (const float*)d_in[1];
    const float* W2 = (const float*)d_in[2];
    const float* W3 = (const float*)d_in[3];
    const float* U1 = (const float*)d_in[4];
    const float* U2 = (const float*)d_in[5];
    const float* U3 = (const float*)d_in[6];
    float* out = (float*)d_out;

    // xw role needs 24512 floats = 98048 B; gru role fits inside. 2 CTAs/SM.
    const int SMEM = (8192 + 12288 + 3072 + 768 + 192) * (int)sizeof(float);
    cudaFuncSetAttribute(fused_kernel,
                         cudaFuncAttributeMaxDynamicSharedMemorySize, SMEM);

    fused_kernel<<<4 * NB, 512, SMEM>>>(x, W1, W2, W3, U1, U2, U3, out);
}